// round 16
// baseline (speedup 1.0000x reference)
#include <cuda_runtime.h>
#include <cstdint>

// Problem constants
#define Bsz  8
#define Nn   2048
#define Fin  512
#define Fout 512

#define BM 128
#define BN 128
#define BK 16
#define PAD 4
#define NTHREADS 256

typedef unsigned long long ull;

// ---------------- scratch (static device globals; no cudaMalloc allowed) ----
__device__ __align__(256) float g_support[(size_t)Bsz * Nn * Fout];   // 33.5 MB
__device__ __align__(256) float g_P1[(size_t)Bsz * Nn * Fin];         // 33.5 MB
__device__ __align__(256) float g_P2[(size_t)Bsz * Nn * Fin];         // 33.5 MB
__device__ __align__(256) float g_adjT[(size_t)Bsz * Nn * Nn];        // 134 MB

// ---------------- packed f32x2 helpers (sm_103a FFMA2 path) ----------------
__device__ __forceinline__ ull pack2(float x) {
    ull r;
    unsigned u = __float_as_uint(x);
    asm("mov.b64 %0, {%1, %1};" : "=l"(r) : "r"(u));
    return r;
}
__device__ __forceinline__ void ffma2(ull& c, ull a, ull b) {
    asm("fma.rn.f32x2 %0, %1, %2, %0;" : "+l"(c) : "l"(a), "l"(b));
}
__device__ __forceinline__ float2 unpack2(ull v) {
    float2 f;
    f.x = __uint_as_float((unsigned)(v & 0xffffffffULL));
    f.y = __uint_as_float((unsigned)(v >> 32));
    return f;
}

// ---------------------------------------------------------------------------
// Generic tiled fp32 GEMM.
//   TA=false: A stored [M,K] row-major.  TA=true: A stored [K,M] row-major.
//   TB=false: B stored [K,N] row-major.  TB=true: B stored [N,K] row-major.
//   C[m,n] = sum_k Aacc[m,k] * Bacc[k,n]  (+ bias[n] if BIAS)
// Requires M%128==0, N%128==0, K%16==0 (true for all call sites here).
// ---------------------------------------------------------------------------
template<bool TA, bool TB, bool BIAS>
__global__ __launch_bounds__(NTHREADS, 1)
void gemm_kernel(const float* __restrict__ Ag, const float* __restrict__ Bg,
                 float* __restrict__ Cg,
                 int M, int N, int K,
                 long long sA, long long sB, long long sC,
                 const float* __restrict__ bias)
{
    __shared__ __align__(16) float As[BK][BM + PAD];
    __shared__ __align__(16) float Bs[BK][BN + PAD];

    const int tid = threadIdx.x;
    const int bz  = blockIdx.z;
    const float* A = Ag + (long long)bz * sA;
    const float* B = Bg + (long long)bz * sB;
    float*       C = Cg + (long long)bz * sC;

    const int m0 = blockIdx.y * BM;
    const int n0 = blockIdx.x * BN;

    // warp/lane mapping: 8 warps as 4(M) x 2(N); lane as 4(M) x 8(N)
    const int warp  = tid >> 5;
    const int lane  = tid & 31;
    const int warpM = warp & 3;
    const int warpN = warp >> 2;
    const int r     = lane >> 3;   // 0..3
    const int c     = lane & 7;    // 0..7
    const int tm    = warpM * 32 + r * 8;   // row offset within tile (mult of 8)
    const int tn    = warpN * 64 + c * 8;   // col offset within tile (mult of 8)

    ull acc[8][4];
    #pragma unroll
    for (int i = 0; i < 8; i++)
        #pragma unroll
        for (int j = 0; j < 4; j++) acc[i][j] = 0ULL;

    const int nk = K / BK;
    float4 ra[2], rb[2];

    // ---- fragment loaders / smem writers -----------------------------------
    auto loadA = [&](int k0) {
        #pragma unroll
        for (int i = 0; i < 2; i++) {
            const int f = tid + i * NTHREADS;
            if (!TA) {
                const int m  = f >> 2;
                const int kq = (f & 3) << 2;
                ra[i] = *(const float4*)(A + (size_t)(m0 + m) * K + (k0 + kq));
            } else {
                const int k  = f >> 5;
                const int mq = (f & 31) << 2;
                ra[i] = *(const float4*)(A + (size_t)(k0 + k) * M + (m0 + mq));
            }
        }
    };
    auto storeA = [&]() {
        #pragma unroll
        for (int i = 0; i < 2; i++) {
            const int f = tid + i * NTHREADS;
            if (!TA) {
                const int m  = f >> 2;
                const int kq = (f & 3) << 2;
                As[kq + 0][m] = ra[i].x;
                As[kq + 1][m] = ra[i].y;
                As[kq + 2][m] = ra[i].z;
                As[kq + 3][m] = ra[i].w;
            } else {
                const int k  = f >> 5;
                const int mq = (f & 31) << 2;
                *(float4*)&As[k][mq] = ra[i];
            }
        }
    };
    auto loadB = [&](int k0) {
        #pragma unroll
        for (int i = 0; i < 2; i++) {
            const int f = tid + i * NTHREADS;
            if (!TB) {
                const int k  = f >> 5;
                const int nq = (f & 31) << 2;
                rb[i] = *(const float4*)(B + (size_t)(k0 + k) * N + (n0 + nq));
            } else {
                const int n  = f >> 2;
                const int kq = (f & 3) << 2;
                rb[i] = *(const float4*)(B + (size_t)(n0 + n) * K + (k0 + kq));
            }
        }
    };
    auto storeB = [&]() {
        #pragma unroll
        for (int i = 0; i < 2; i++) {
            const int f = tid + i * NTHREADS;
            if (!TB) {
                const int k  = f >> 5;
                const int nq = (f & 31) << 2;
                *(float4*)&Bs[k][nq] = rb[i];
            } else {
                const int n  = f >> 2;
                const int kq = (f & 3) << 2;
                Bs[kq + 0][n] = rb[i].x;
                Bs[kq + 1][n] = rb[i].y;
                Bs[kq + 2][n] = rb[i].z;
                Bs[kq + 3][n] = rb[i].w;
            }
        }
    };

    // ---- mainloop with register prefetch -----------------------------------
    loadA(0); loadB(0);
    storeA(); storeB();
    __syncthreads();

    for (int kt = 0; kt < nk; kt++) {
        const bool has_next = (kt + 1 < nk);
        if (has_next) { loadA((kt + 1) * BK); loadB((kt + 1) * BK); }

        #pragma unroll
        for (int kk = 0; kk < BK; kk++) {
            const float4 a0 = *(const float4*)&As[kk][tm];
            const float4 a1 = *(const float4*)&As[kk][tm + 4];
            const double* bp = (const double*)&Bs[kk][tn];
            const double bd0 = bp[0], bd1 = bp[1], bd2 = bp[2], bd3 = bp[3];
            ull bb[4];
            bb[0] = __double_as_longlong(bd0);
            bb[1] = __double_as_longlong(bd1);
            bb[2] = __double_as_longlong(bd2);
            bb[3] = __double_as_longlong(bd3);
            const float av[8] = {a0.x, a0.y, a0.z, a0.w, a1.x, a1.y, a1.z, a1.w};
            #pragma unroll
            for (int i = 0; i < 8; i++) {
                const ull aa = pack2(av[i]);
                #pragma unroll
                for (int j = 0; j < 4; j++) ffma2(acc[i][j], aa, bb[j]);
            }
        }
        __syncthreads();
        if (has_next) { storeA(); storeB(); __syncthreads(); }
    }

    // ---- epilogue -----------------------------------------------------------
    float bv[8];
    if (BIAS) {
        #pragma unroll
        for (int j = 0; j < 8; j++) bv[j] = bias[n0 + tn + j];
    }
    #pragma unroll
    for (int i = 0; i < 8; i++) {
        float o[8];
        #pragma unroll
        for (int j = 0; j < 4; j++) {
            const float2 v = unpack2(acc[i][j]);
            o[2 * j]     = v.x;
            o[2 * j + 1] = v.y;
        }
        if (BIAS) {
            #pragma unroll
            for (int j = 0; j < 8; j++) o[j] += bv[j];
        }
        float4* cp = (float4*)(C + (size_t)(m0 + tm + i) * N + (n0 + tn));
        cp[0] = make_float4(o[0], o[1], o[2], o[3]);
        cp[1] = make_float4(o[4], o[5], o[6], o[7]);
    }
}

// ---------------------------------------------------------------------------
// In-place softmax over the last (contiguous) dim of adjT: rows of 2048.
// One 256-thread block per row; 8 elements per thread (float4 x2 coalesced).
// ---------------------------------------------------------------------------
__global__ __launch_bounds__(256)
void softmax_kernel(float* __restrict__ data)
{
    const int t = threadIdx.x;
    float* row = data + (size_t)blockIdx.x * Nn;

    const float4 v0 = ((const float4*)row)[t];
    const float4 v1 = ((const float4*)row)[t + 256];
    float vals[8] = {v0.x, v0.y, v0.z, v0.w, v1.x, v1.y, v1.z, v1.w};

    float m = vals[0];
    #pragma unroll
    for (int i = 1; i < 8; i++) m = fmaxf(m, vals[i]);
    #pragma unroll
    for (int o = 16; o; o >>= 1) m = fmaxf(m, __shfl_xor_sync(0xffffffffu, m, o));

    __shared__ float red[8];
    const int warp = t >> 5, lane = t & 31;
    if (lane == 0) red[warp] = m;
    __syncthreads();
    float bm = red[0];
    #pragma unroll
    for (int w = 1; w < 8; w++) bm = fmaxf(bm, red[w]);

    float s = 0.f;
    #pragma unroll
    for (int i = 0; i < 8; i++) { vals[i] = __expf(vals[i] - bm); s += vals[i]; }
    #pragma unroll
    for (int o = 16; o; o >>= 1) s += __shfl_xor_sync(0xffffffffu, s, o);
    __syncthreads();
    if (lane == 0) red[warp] = s;
    __syncthreads();
    float tot = 0.f;
    #pragma unroll
    for (int w = 0; w < 8; w++) tot += red[w];

    const float inv = 1.0f / tot;
    #pragma unroll
    for (int i = 0; i < 8; i++) vals[i] *= inv;

    ((float4*)row)[t]       = make_float4(vals[0], vals[1], vals[2], vals[3]);
    ((float4*)row)[t + 256] = make_float4(vals[4], vals[5], vals[6], vals[7]);
}

// ---------------------------------------------------------------------------
extern "C" void kernel_launch(void* const* d_in, const int* in_sizes, int n_in,
                              void* d_out, int out_size)
{
    (void)in_sizes; (void)n_in; (void)out_size;
    const float* x      = (const float*)d_in[0];   // [8,2048,512]
    const float* weight = (const float*)d_in[1];   // [512,512]
    const float* bias   = (const float*)d_in[2];   // [512]
    const float* w1     = (const float*)d_in[3];   // [512,512]
    const float* w2     = (const float*)d_in[4];   // [512,512]
    float* out          = (float*)d_out;           // [8,2048,512]

    float *support, *P1, *P2, *adjT;
    cudaGetSymbolAddress((void**)&support, g_support);
    cudaGetSymbolAddress((void**)&P1,      g_P1);
    cudaGetSymbolAddress((void**)&P2,      g_P2);
    cudaGetSymbolAddress((void**)&adjT,    g_adjT);

    const dim3 blk(NTHREADS);
    const int MB = Bsz * Nn;   // 16384: flatten (b,n) for the first three GEMMs

    // support = x @ weight                        [16384,512] = [16384,512]x[512,512]
    gemm_kernel<false, false, false><<<dim3(Fout / BN, MB / BM, 1), blk>>>(
        x, weight, support, MB, Fout, Fin, 0, 0, 0, nullptr);

    // P1 = x @ w1^T    (B stored [N=512 out-rows, K=512])
    gemm_kernel<false, true, false><<<dim3(Fin / BN, MB / BM, 1), blk>>>(
        x, w1, P1, MB, Fin, Fin, 0, 0, 0, nullptr);

    // P2 = x @ w2^T
    gemm_kernel<false, true, false><<<dim3(Fin / BN, MB / BM, 1), blk>>>(
        x, w2, P2, MB, Fin, Fin, 0, 0, 0, nullptr);

    // adjT[b] = P2[b] @ P1[b]^T : adjT[b,m,n] = sum_e P2[b,m,e] P1[b,n,e]
    gemm_kernel<false, true, false><<<dim3(Nn / BN, Nn / BM, Bsz), blk>>>(
        P2, P1, adjT, Nn, Nn, Fin,
        (long long)Nn * Fin, (long long)Nn * Fin, (long long)Nn * Nn, nullptr);

    // softmax over last dim of adjT (== axis=1 of adj), in place
    softmax_kernel<<<Bsz * Nn, 256>>>(adjT);

    // out[b] = adjT[b]^T @ support[b] + bias  (A stored [K=2048(m), M=2048(n)])
    gemm_kernel<true, false, true><<<dim3(Fout / BN, Nn / BM, Bsz), blk>>>(
        adjT, support, out, Nn, Fout, Nn,
        (long long)Nn * Nn, (long long)Nn * Fout, (long long)Nn * Fout, bias);
}

// round 17
// speedup vs baseline: 1.0018x; 1.0018x over previous
#include <cuda_runtime.h>
#include <cstdint>

// Problem constants
#define Bsz  8
#define Nn   2048
#define Fin  512
#define Fout 512

#define BM 128
#define BN 128
#define BK 16
#define PAD 4
#define NTHREADS 256

typedef unsigned long long ull;

// ---------------- scratch (static device globals; no cudaMalloc allowed) ----
__device__ __align__(256) float g_support[(size_t)Bsz * Nn * Fout];   // 33.5 MB
__device__ __align__(256) float g_P1[(size_t)Bsz * Nn * Fin];         // 33.5 MB
__device__ __align__(256) float g_P2[(size_t)Bsz * Nn * Fin];         // 33.5 MB
__device__ __align__(256) float g_adjT[(size_t)Bsz * Nn * Nn];        // 134 MB

// ---------------- packed f32x2 helpers (sm_103a FFMA2 path) ----------------
__device__ __forceinline__ ull pack2(float x) {
    ull r;
    unsigned u = __float_as_uint(x);
    asm("mov.b64 %0, {%1, %1};" : "=l"(r) : "r"(u));
    return r;
}
__device__ __forceinline__ void ffma2(ull& c, ull a, ull b) {
    asm("fma.rn.f32x2 %0, %1, %2, %0;" : "+l"(c) : "l"(a), "l"(b));
}
__device__ __forceinline__ float2 unpack2(ull v) {
    float2 f;
    f.x = __uint_as_float((unsigned)(v & 0xffffffffULL));
    f.y = __uint_as_float((unsigned)(v >> 32));
    return f;
}

// ---------------------------------------------------------------------------
// Generic tiled fp32 GEMM.
//   TA=false: A stored [M,K] row-major.  TA=true: A stored [K,M] row-major.
//   TB=false: B stored [K,N] row-major.  TB=true: B stored [N,K] row-major.
//   C[m,n] = sum_k Aacc[m,k] * Bacc[k,n]  (+ bias[n] if BIAS)
// Requires M%128==0, N%128==0, K%16==0 (true for all call sites here).
// ---------------------------------------------------------------------------
template<bool TA, bool TB, bool BIAS>
__global__ __launch_bounds__(NTHREADS, 1)
void gemm_kernel(const float* __restrict__ Ag, const float* __restrict__ Bg,
                 float* __restrict__ Cg,
                 int M, int N, int K,
                 long long sA, long long sB, long long sC,
                 const float* __restrict__ bias)
{
    __shared__ __align__(16) float As[BK][BM + PAD];
    __shared__ __align__(16) float Bs[BK][BN + PAD];

    const int tid = threadIdx.x;
    const int bz  = blockIdx.z;
    const float* A = Ag + (long long)bz * sA;
    const float* B = Bg + (long long)bz * sB;
    float*       C = Cg + (long long)bz * sC;

    const int m0 = blockIdx.y * BM;
    const int n0 = blockIdx.x * BN;

    // warp/lane mapping: 8 warps as 4(M) x 2(N); lane as 4(M) x 8(N)
    const int warp  = tid >> 5;
    const int lane  = tid & 31;
    const int warpM = warp & 3;
    const int warpN = warp >> 2;
    const int r     = lane >> 3;   // 0..3
    const int c     = lane & 7;    // 0..7
    const int tm    = warpM * 32 + r * 8;   // row offset within tile (mult of 8)
    const int tn    = warpN * 64 + c * 8;   // col offset within tile (mult of 8)

    ull acc[8][4];
    #pragma unroll
    for (int i = 0; i < 8; i++)
        #pragma unroll
        for (int j = 0; j < 4; j++) acc[i][j] = 0ULL;

    const int nk = K / BK;
    float4 ra[2], rb[2];

    // ---- fragment loaders / smem writers -----------------------------------
    auto loadA = [&](int k0) {
        #pragma unroll
        for (int i = 0; i < 2; i++) {
            const int f = tid + i * NTHREADS;
            if (!TA) {
                const int m  = f >> 2;
                const int kq = (f & 3) << 2;
                ra[i] = *(const float4*)(A + (size_t)(m0 + m) * K + (k0 + kq));
            } else {
                const int k  = f >> 5;
                const int mq = (f & 31) << 2;
                ra[i] = *(const float4*)(A + (size_t)(k0 + k) * M + (m0 + mq));
            }
        }
    };
    auto storeA = [&]() {
        #pragma unroll
        for (int i = 0; i < 2; i++) {
            const int f = tid + i * NTHREADS;
            if (!TA) {
                const int m  = f >> 2;
                const int kq = (f & 3) << 2;
                As[kq + 0][m] = ra[i].x;
                As[kq + 1][m] = ra[i].y;
                As[kq + 2][m] = ra[i].z;
                As[kq + 3][m] = ra[i].w;
            } else {
                const int k  = f >> 5;
                const int mq = (f & 31) << 2;
                *(float4*)&As[k][mq] = ra[i];
            }
        }
    };
    auto loadB = [&](int k0) {
        #pragma unroll
        for (int i = 0; i < 2; i++) {
            const int f = tid + i * NTHREADS;
            if (!TB) {
                const int k  = f >> 5;
                const int nq = (f & 31) << 2;
                rb[i] = *(const float4*)(B + (size_t)(k0 + k) * N + (n0 + nq));
            } else {
                const int n  = f >> 2;
                const int kq = (f & 3) << 2;
                rb[i] = *(const float4*)(B + (size_t)(n0 + n) * K + (k0 + kq));
            }
        }
    };
    auto storeB = [&]() {
        #pragma unroll
        for (int i = 0; i < 2; i++) {
            const int f = tid + i * NTHREADS;
            if (!TB) {
                const int k  = f >> 5;
                const int nq = (f & 31) << 2;
                *(float4*)&Bs[k][nq] = rb[i];
            } else {
                const int n  = f >> 2;
                const int kq = (f & 3) << 2;
                Bs[kq + 0][n] = rb[i].x;
                Bs[kq + 1][n] = rb[i].y;
                Bs[kq + 2][n] = rb[i].z;
                Bs[kq + 3][n] = rb[i].w;
            }
        }
    };

    // ---- mainloop with register prefetch -----------------------------------
    loadA(0); loadB(0);
    storeA(); storeB();
    __syncthreads();

    for (int kt = 0; kt < nk; kt++) {
        const bool has_next = (kt + 1 < nk);
        if (has_next) { loadA((kt + 1) * BK); loadB((kt + 1) * BK); }

        #pragma unroll
        for (int kk = 0; kk < BK; kk++) {
            const float4 a0 = *(const float4*)&As[kk][tm];
            const float4 a1 = *(const float4*)&As[kk][tm + 4];
            const double* bp = (const double*)&Bs[kk][tn];
            const double bd0 = bp[0], bd1 = bp[1], bd2 = bp[2], bd3 = bp[3];
            ull bb[4];
            bb[0] = __double_as_longlong(bd0);
            bb[1] = __double_as_longlong(bd1);
            bb[2] = __double_as_longlong(bd2);
            bb[3] = __double_as_longlong(bd3);
            const float av[8] = {a0.x, a0.y, a0.z, a0.w, a1.x, a1.y, a1.z, a1.w};
            #pragma unroll
            for (int i = 0; i < 8; i++) {
                const ull aa = pack2(av[i]);
                #pragma unroll
                for (int j = 0; j < 4; j++) ffma2(acc[i][j], aa, bb[j]);
            }
        }
        __syncthreads();
        if (has_next) { storeA(); storeB(); __syncthreads(); }
    }

    // ---- epilogue -----------------------------------------------------------
    float bv[8];
    if (BIAS) {
        #pragma unroll
        for (int j = 0; j < 8; j++) bv[j] = bias[n0 + tn + j];
    }
    #pragma unroll
    for (int i = 0; i < 8; i++) {
        float o[8];
        #pragma unroll
        for (int j = 0; j < 4; j++) {
            const float2 v = unpack2(acc[i][j]);
            o[2 * j]     = v.x;
            o[2 * j + 1] = v.y;
        }
        if (BIAS) {
            #pragma unroll
            for (int j = 0; j < 8; j++) o[j] += bv[j];
        }
        float4* cp = (float4*)(C + (size_t)(m0 + tm + i) * N + (n0 + tn));
        cp[0] = make_float4(o[0], o[1], o[2], o[3]);
        cp[1] = make_float4(o[4], o[5], o[6], o[7]);
    }
}

// ---------------------------------------------------------------------------
// In-place softmax over the last (contiguous) dim of adjT: rows of 2048.
// One 256-thread block per row; 8 elements per thread (float4 x2 coalesced).
// ---------------------------------------------------------------------------
__global__ __launch_bounds__(256)
void softmax_kernel(float* __restrict__ data)
{
    const int t = threadIdx.x;
    float* row = data + (size_t)blockIdx.x * Nn;

    const float4 v0 = ((const float4*)row)[t];
    const float4 v1 = ((const float4*)row)[t + 256];
    float vals[8] = {v0.x, v0.y, v0.z, v0.w, v1.x, v1.y, v1.z, v1.w};

    float m = vals[0];
    #pragma unroll
    for (int i = 1; i < 8; i++) m = fmaxf(m, vals[i]);
    #pragma unroll
    for (int o = 16; o; o >>= 1) m = fmaxf(m, __shfl_xor_sync(0xffffffffu, m, o));

    __shared__ float red[8];
    const int warp = t >> 5, lane = t & 31;
    if (lane == 0) red[warp] = m;
    __syncthreads();
    float bm = red[0];
    #pragma unroll
    for (int w = 1; w < 8; w++) bm = fmaxf(bm, red[w]);

    float s = 0.f;
    #pragma unroll
    for (int i = 0; i < 8; i++) { vals[i] = __expf(vals[i] - bm); s += vals[i]; }
    #pragma unroll
    for (int o = 16; o; o >>= 1) s += __shfl_xor_sync(0xffffffffu, s, o);
    __syncthreads();
    if (lane == 0) red[warp] = s;
    __syncthreads();
    float tot = 0.f;
    #pragma unroll
    for (int w = 0; w < 8; w++) tot += red[w];

    const float inv = 1.0f / tot;
    #pragma unroll
    for (int i = 0; i < 8; i++) vals[i] *= inv;

    ((float4*)row)[t]       = make_float4(vals[0], vals[1], vals[2], vals[3]);
    ((float4*)row)[t + 256] = make_float4(vals[4], vals[5], vals[6], vals[7]);
}

// ---------------------------------------------------------------------------
extern "C" void kernel_launch(void* const* d_in, const int* in_sizes, int n_in,
                              void* d_out, int out_size)
{
    (void)in_sizes; (void)n_in; (void)out_size;
    const float* x      = (const float*)d_in[0];   // [8,2048,512]
    const float* weight = (const float*)d_in[1];   // [512,512]
    const float* bias   = (const float*)d_in[2];   // [512]
    const float* w1     = (const float*)d_in[3];   // [512,512]
    const float* w2     = (const float*)d_in[4];   // [512,512]
    float* out          = (float*)d_out;           // [8,2048,512]

    float *support, *P1, *P2, *adjT;
    cudaGetSymbolAddress((void**)&support, g_support);
    cudaGetSymbolAddress((void**)&P1,      g_P1);
    cudaGetSymbolAddress((void**)&P2,      g_P2);
    cudaGetSymbolAddress((void**)&adjT,    g_adjT);

    const dim3 blk(NTHREADS);
    const int MB = Bsz * Nn;   // 16384: flatten (b,n) for the first three GEMMs

    // support = x @ weight                        [16384,512] = [16384,512]x[512,512]
    gemm_kernel<false, false, false><<<dim3(Fout / BN, MB / BM, 1), blk>>>(
        x, weight, support, MB, Fout, Fin, 0, 0, 0, nullptr);

    // P1 = x @ w1^T    (B stored [N=512 out-rows, K=512])
    gemm_kernel<false, true, false><<<dim3(Fin / BN, MB / BM, 1), blk>>>(
        x, w1, P1, MB, Fin, Fin, 0, 0, 0, nullptr);

    // P2 = x @ w2^T
    gemm_kernel<false, true, false><<<dim3(Fin / BN, MB / BM, 1), blk>>>(
        x, w2, P2, MB, Fin, Fin, 0, 0, 0, nullptr);

    // adjT[b] = P2[b] @ P1[b]^T : adjT[b,m,n] = sum_e P2[b,m,e] P1[b,n,e]
    gemm_kernel<false, true, false><<<dim3(Nn / BN, Nn / BM, Bsz), blk>>>(
        P2, P1, adjT, Nn, Nn, Fin,
        (long long)Nn * Fin, (long long)Nn * Fin, (long long)Nn * Nn, nullptr);

    // softmax over last dim of adjT (== axis=1 of adj), in place
    softmax_kernel<<<Bsz * Nn, 256>>>(adjT);

    // out[b] = adjT[b]^T @ support[b] + bias  (A stored [K=2048(m), M=2048(n)])
    gemm_kernel<true, false, true><<<dim3(Fout / BN, Nn / BM, Bsz), blk>>>(
        adjT, support, out, Nn, Fout, Nn,
        (long long)Nn * Nn, (long long)Nn * Fout, (long long)Nn * Fout, bias);
}